// round 13
// baseline (speedup 1.0000x reference)
#include <cuda_runtime.h>
#include <cuda_bf16.h>
#include <math.h>

#define N_TOKENS 131072
#define HIDDEN   1024
#define CL       64
#define EXPERTS  64

// Scratch (allocation-free rule: __device__ globals)
__device__ float g_h[N_TOKENS * CL];       // gelu(xW+b), 32 MB
__device__ float g_cn[EXPERTS * CL];       // normalized centroids
__device__ float g_cc[EXPERTS];            // sum of squares of normalized centroids

// ---------------------------------------------------------------------------
// Eigen/XLA erf (fused pmadd Horner) — best output-0 agreement (R10)
// ---------------------------------------------------------------------------
__device__ __forceinline__ float eigen_erf(float x) {
    x = fmaxf(fminf(x, 4.0f), -4.0f);
    float x2 = __fmul_rn(x, x);
    float p = fmaf(x2, -2.72614225801306e-10f, 2.77068142495902e-08f);
    p = fmaf(x2, p, -2.10102402082508e-06f);
    p = fmaf(x2, p, -5.69250639462346e-05f);
    p = fmaf(x2, p, -7.34990630326855e-04f);
    p = fmaf(x2, p, -2.95459980854025e-03f);
    p = fmaf(x2, p, -1.60960333262415e-02f);
    p = __fmul_rn(x, p);
    float q = fmaf(x2, -1.45660718464996e-05f, -2.13374055278905e-04f);
    q = fmaf(x2, q, -1.68282697438203e-03f);
    q = fmaf(x2, q, -7.37332916720468e-03f);
    q = fmaf(x2, q, -1.42647390514189e-02f);
    return __fdiv_rn(p, q);
}

__device__ __forceinline__ float xla_gelu(float v) {
    float t = __fmul_rn(v, __int_as_float(0x3F3504F3));  // * 1/sqrt(2) folded
    float e = eigen_erf(t);
    float r = __fmul_rn(v, __fadd_rn(e, 1.0f));
    return __fmul_rn(r, 0.5f);
}

// XLA:CPU runtime exp (Eigen/Cephes): fused poly, unfused Cody-Waite (R10)
__device__ __forceinline__ float xla_exp(float x) {
    x = fminf(x, 88.3762626647950f);
    x = fmaxf(x, -88.3762626647949f);
    float fx = fmaf(x, 1.44269504088896341f, 0.5f);
    fx = floorf(fx);
    float tmp = __fmul_rn(fx, 0.693359375f);
    float z   = __fmul_rn(fx, -2.12194440e-4f);
    x = __fsub_rn(x, tmp);
    x = __fsub_rn(x, z);
    z = __fmul_rn(x, x);
    float y = 1.9875691500E-4f;
    y = fmaf(y, x, 1.3981999507E-3f);
    y = fmaf(y, x, 8.3334519073E-3f);
    y = fmaf(y, x, 4.1665795894E-2f);
    y = fmaf(y, x, 1.6666665459E-1f);
    y = fmaf(y, x, 5.0000001201E-1f);
    y = fmaf(y, z, x);
    y = __fadd_rn(y, 1.0f);
    int n = (int)fx;
    float p2n = __int_as_float((n + 127) << 23);
    return __fmul_rn(y, p2n);
}

// 8-lane strided row-reduce, unfused body, halving horizontal (R10)
__device__ __forceinline__ float vsum_sq64(const float* v) {
    float a[8];
    #pragma unroll
    for (int l = 0; l < 8; l++) a[l] = 0.f;
    #pragma unroll
    for (int i = 0; i < 8; i++)
        #pragma unroll
        for (int l = 0; l < 8; l++)
            a[l] = __fadd_rn(a[l], __fmul_rn(v[8 * i + l], v[8 * i + l]));
    float b0 = __fadd_rn(a[0], a[4]);
    float b1 = __fadd_rn(a[1], a[5]);
    float b2 = __fadd_rn(a[2], a[6]);
    float b3 = __fadd_rn(a[3], a[7]);
    return __fadd_rn(__fadd_rn(b0, b2), __fadd_rn(b1, b3));
}

__device__ __forceinline__ float vsum64(const float* v) {
    float a[8];
    #pragma unroll
    for (int l = 0; l < 8; l++) a[l] = 0.f;
    #pragma unroll
    for (int i = 0; i < 8; i++)
        #pragma unroll
        for (int l = 0; l < 8; l++)
            a[l] = __fadd_rn(a[l], v[8 * i + l]);
    float b0 = __fadd_rn(a[0], a[4]);
    float b1 = __fadd_rn(a[1], a[5]);
    float b2 = __fadd_rn(a[2], a[6]);
    float b3 = __fadd_rn(a[3], a[7]);
    return __fadd_rn(__fadd_rn(b0, b2), __fadd_rn(b1, b3));
}

// ---------------------------------------------------------------------------
// Kernel 0: normalize centroids (R10)
// ---------------------------------------------------------------------------
__global__ void centroid_norm_kernel(const float* __restrict__ centroids) {
    int e = threadIdx.x;
    if (e >= EXPERTS) return;
    float c[CL];
    for (int j = 0; j < CL; j++) c[j] = centroids[e * CL + j];
    float ss = vsum_sq64(c);
    float nrm = fmaxf(__fsqrt_rn(ss), 1e-8f);
    float cn[CL];
    for (int j = 0; j < CL; j++) {
        cn[j] = __fdiv_rn(c[j], nrm);
        g_cn[e * CL + j] = cn[j];
    }
    g_cc[e] = vsum_sq64(cn);
}

// ---------------------------------------------------------------------------
// Kernel 1: fp32 tiled GEMM  h = gelu(x @ W + b)
// NEW: Eigen kc-panel segmentation — k accumulated in 2 chains of 512,
// combined with one rounded fp32 add (panel C-update rounding).
// ---------------------------------------------------------------------------
#define BM 128
#define BN 64
#define BK 16
#define KSEG 512

__global__ __launch_bounds__(256, 2)
void gemm_gelu_kernel(const float* __restrict__ x,
                      const float* __restrict__ W,
                      const float* __restrict__ b) {
    __shared__ float As[BK][BM];
    __shared__ float Bs[BK][BN];

    const int tid = threadIdx.x;
    const int m0  = blockIdx.x * BM;
    const int tn  = tid & 15;
    const int tm  = tid >> 4;

    const int arow = tid >> 2;
    const int ac4  = tid & 3;
    const int brow = tid >> 4;
    const int bc4  = tid & 15;

    float acc[8][4];     // current kc-panel chain
    float accp[8][4];    // folded previous panels
    #pragma unroll
    for (int i = 0; i < 8; i++)
        #pragma unroll
        for (int j = 0; j < 4; j++) { acc[i][j] = 0.f; accp[i][j] = 0.f; }

    for (int k0 = 0; k0 < HIDDEN; k0 += BK) {
        if (k0 == KSEG) {
            // panel boundary: fold current chain into C (rounded add), reset
            #pragma unroll
            for (int i = 0; i < 8; i++)
                #pragma unroll
                for (int j = 0; j < 4; j++) {
                    accp[i][j] = __fadd_rn(accp[i][j], acc[i][j]);
                    acc[i][j] = 0.f;
                }
        }

        float4 a0 = *(const float4*)&x[(size_t)(m0 + arow)      * HIDDEN + k0 + ac4 * 4];
        float4 a1 = *(const float4*)&x[(size_t)(m0 + arow + 64) * HIDDEN + k0 + ac4 * 4];
        float4 bb = *(const float4*)&W[(size_t)(k0 + brow) * CL + bc4 * 4];

        __syncthreads();

        As[ac4 * 4 + 0][arow] = a0.x;
        As[ac4 * 4 + 1][arow] = a0.y;
        As[ac4 * 4 + 2][arow] = a0.z;
        As[ac4 * 4 + 3][arow] = a0.w;
        As[ac4 * 4 + 0][arow + 64] = a1.x;
        As[ac4 * 4 + 1][arow + 64] = a1.y;
        As[ac4 * 4 + 2][arow + 64] = a1.z;
        As[ac4 * 4 + 3][arow + 64] = a1.w;
        *(float4*)&Bs[brow][bc4 * 4] = bb;

        __syncthreads();

        #pragma unroll
        for (int kk = 0; kk < BK; kk++) {
            float af[8], bf[4];
            *(float4*)&af[0] = *(const float4*)&As[kk][tm * 8 + 0];
            *(float4*)&af[4] = *(const float4*)&As[kk][tm * 8 + 4];
            *(float4*)&bf[0] = *(const float4*)&Bs[kk][tn * 4];
            #pragma unroll
            for (int i = 0; i < 8; i++)
                #pragma unroll
                for (int j = 0; j < 4; j++)
                    acc[i][j] = fmaf(af[i], bf[j], acc[i][j]);
        }
    }

    float bias[4];
    #pragma unroll
    for (int j = 0; j < 4; j++) bias[j] = __ldg(&b[tn * 4 + j]);

    #pragma unroll
    for (int i = 0; i < 8; i++) {
        int m = m0 + tm * 8 + i;
        float4 o;
        float v;
        v = __fadd_rn(__fadd_rn(accp[i][0], acc[i][0]), bias[0]); o.x = xla_gelu(v);
        v = __fadd_rn(__fadd_rn(accp[i][1], acc[i][1]), bias[1]); o.y = xla_gelu(v);
        v = __fadd_rn(__fadd_rn(accp[i][2], acc[i][2]), bias[2]); o.z = xla_gelu(v);
        v = __fadd_rn(__fadd_rn(accp[i][3], acc[i][3]), bias[3]); o.w = xla_gelu(v);
        *(float4*)&g_h[(size_t)m * CL + tn * 4] = o;
    }
}

// ---------------------------------------------------------------------------
// Kernel 2: per-token normalize -> cdist -> softmax(max-sub) -> top-2 (R10)
// ---------------------------------------------------------------------------
__global__ __launch_bounds__(256)
void router_epilogue_kernel(float* __restrict__ out) {
    __shared__ float cn_s[EXPERTS * CL];
    __shared__ float cc_s[EXPERTS];

    const int tid = threadIdx.x;
    for (int i = tid; i < EXPERTS * CL; i += 256) cn_s[i] = g_cn[i];
    if (tid < EXPERTS) cc_s[tid] = g_cc[tid];
    __syncthreads();

    const int t = blockIdx.x * 256 + tid;

    float d[CL];
    #pragma unroll
    for (int i = 0; i < CL / 4; i++)
        *(float4*)&d[i * 4] = *(const float4*)&g_h[(size_t)t * CL + i * 4];

    float ss  = vsum_sq64(d);
    float nrm = fmaxf(__fsqrt_rn(ss), 1e-8f);
    #pragma unroll
    for (int j = 0; j < CL; j++) d[j] = __fdiv_rn(d[j], nrm);
    float dd = vsum_sq64(d);

    // pass 1: -dist per expert (fused ascending dot), track max
    float nd[EXPERTS];
    float ndmax = -INFINITY;
    for (int e = 0; e < EXPERTS; e++) {
        float dot = 0.f;
        #pragma unroll
        for (int j = 0; j < CL; j++)
            dot = fmaf(d[j], cn_s[e * CL + j], dot);
        float sq   = __fsub_rn(__fadd_rn(dd, cc_s[e]), __fmul_rn(2.0f, dot));
        float dist = __fsqrt_rn(fmaxf(sq, 0.0f));
        float v = -dist;
        nd[e] = v;
        ndmax = fmaxf(ndmax, v);
    }

    // pass 2: w = exp(x - xmax)
    #pragma unroll
    for (int e = 0; e < EXPERTS; e++)
        nd[e] = xla_exp(__fsub_rn(nd[e], ndmax));
    float sum = vsum64(nd);

    // pass 3: p = w / sum, stable top-2 (ties -> lower index)
    float p1 = -1.f, p2 = -1.f;
    int   i1 = 0,    i2 = 0;
    for (int e = 0; e < EXPERTS; e++) {
        float p = __fdiv_rn(nd[e], sum);
        if (p > p1)      { p2 = p1; i2 = i1; p1 = p; i1 = e; }
        else if (p > p2) { p2 = p; i2 = e; }
    }

    out[(size_t)t * 2 + 0] = p1;
    out[(size_t)t * 2 + 1] = p2;
    float* oi = out + (size_t)N_TOKENS * 2;
    oi[(size_t)t * 2 + 0] = (float)i1;
    oi[(size_t)t * 2 + 1] = (float)i2;
}

// ---------------------------------------------------------------------------
extern "C" void kernel_launch(void* const* d_in, const int* in_sizes, int n_in,
                              void* d_out, int out_size) {
    const float* x         = (const float*)d_in[0];
    const float* W         = (const float*)d_in[1];
    const float* b         = (const float*)d_in[2];
    const float* centroids = (const float*)d_in[3];
    float* out = (float*)d_out;

    centroid_norm_kernel<<<1, 64>>>(centroids);
    gemm_gelu_kernel<<<N_TOKENS / BM, 256>>>(x, W, b);
    router_epilogue_kernel<<<N_TOKENS / 256, 256>>>(out);
}